// round 10
// baseline (speedup 1.0000x reference)
#include <cuda_runtime.h>
#include <math.h>

// Problem dims
#define BB   64      // batch
#define TT   512     // seq len
#define EE   256     // embed
#define HH   512     // hidden
#define GG   2048    // 4*HH
#define KC   64      // k-chunk
#define WSTR 36      // weight tile row stride (32 cols + pad, 16B-aligned rows)

// ---------------- device scratch (allocation-free) ----------------
__device__ float g_X[TT * EE * BB];        // [t][e][b]  33.5 MB
__device__ float g_h1[2][2][HH * BB];      // [dir][parity][k][b]
__device__ float g_h2[2][2][HH * BB];
__device__ unsigned g_bar[2];
__device__ int g_tok32;                    // 1 if tokens are int32

// ---------------- helpers ----------------
__device__ __forceinline__ float fsig(float x) { return 1.0f / (1.0f + __expf(-x)); }
__device__ __forceinline__ float ftanh(float x) {
    return 2.0f / (1.0f + __expf(-2.0f * x)) - 1.0f;
}

__device__ __forceinline__ void ffma2(unsigned long long& d,
                                      unsigned long long a,
                                      unsigned long long b) {
    asm("fma.rn.f32x2 %0, %1, %2, %0;" : "+l"(d) : "l"(a), "l"(b));
}

__device__ __forceinline__ void grid_bar(unsigned* ctr, unsigned target) {
    __syncthreads();
    if (threadIdx.x == 0) {
        __threadfence();                 // release our h writes to GPU scope
        atomicAdd(ctr, 1u);
        while (*((volatile unsigned*)ctr) < target) { }
    }
    __syncthreads();
}

// ---------------- reset ----------------
__global__ void reset_kernel() {
    int i = blockIdx.x * blockDim.x + threadIdx.x;
    if (i < HH * BB) {
        #pragma unroll
        for (int d = 0; d < 2; d++)
            #pragma unroll
            for (int p = 0; p < 2; p++) { g_h1[d][p][i] = 0.0f; g_h2[d][p][i] = 0.0f; }
    }
    if (i == 0) { g_bar[0] = 0u; g_bar[1] = 0u; }
}

// ---------------- token dtype detect ----------------
// If tokens are int64 little-endian with values < 50000, every odd 32-bit word is 0.
__global__ void detect_kernel(const unsigned* tok) {
    __shared__ unsigned red[256];
    unsigned v = 0;
    for (int i = threadIdx.x; i < 16384; i += 256) v |= tok[2 * i + 1];
    red[threadIdx.x] = v;
    __syncthreads();
    for (int s = 128; s > 0; s >>= 1) {
        if (threadIdx.x < s) red[threadIdx.x] |= red[threadIdx.x + s];
        __syncthreads();
    }
    if (threadIdx.x == 0) g_tok32 = (red[0] != 0u) ? 1 : 0;
}

// ---------------- embedding gather (X[t][e][b]) ----------------
__global__ void gather_kernel(const void* tokens, const float* emb) {
    int t = blockIdx.x;        // 0..511
    int b = blockIdx.y;        // 0..63
    int e = threadIdx.x;       // 0..255
    long idx;
    if (g_tok32) idx = (long)((const int*)tokens)[b * TT + t];
    else         idx = (long)((const unsigned*)tokens)[(size_t)(b * TT + t) * 2];
    g_X[((size_t)t * EE + e) * BB + b] = emb[idx * EE + e];
}

// ---------------- GEMM chunk helper (R2 structure, FFMA2 inner loop) ----------
// acc2[j] pairs cols (2j, 2j+1) of this thread's 8 gate columns.
__device__ __forceinline__ void gemm_chunks(
    unsigned long long acc2[4], const float* __restrict__ src, int nk,
    const float* __restrict__ Wg, int ub,
    int tid, int b, int cg, float* wt, float* ht)
{
    const int skl = tid & 63;       // k-local row this thread stages
    const int sseg = tid >> 6;      // gate segment this thread stages
    for (int k0 = 0; k0 < nk; k0 += KC) {
        // prefetch into registers (overlaps previous chunk's compute)
        const float4* wsrc = (const float4*)(Wg + (size_t)(k0 + skl) * GG + sseg * HH + ub);
        float4 wv0 = wsrc[0];
        float4 wv1 = wsrc[1];
        const float4* hsrc = (const float4*)(src + (size_t)k0 * BB);
        float4 h0 = __ldcg(hsrc + tid);
        float4 h1 = __ldcg(hsrc + tid + 256);
        float4 h2 = __ldcg(hsrc + tid + 512);
        float4 h3 = __ldcg(hsrc + tid + 768);
        __syncthreads();   // previous chunk's compute done before overwrite
        ((float4*)(wt + skl * WSTR + sseg * 8))[0] = wv0;
        ((float4*)(wt + skl * WSTR + sseg * 8))[1] = wv1;
        ((float4*)ht)[tid      ] = h0;
        ((float4*)ht)[tid + 256] = h1;
        ((float4*)ht)[tid + 512] = h2;
        ((float4*)ht)[tid + 768] = h3;
        __syncthreads();
        #pragma unroll 16
        for (int k = 0; k < KC; k++) {
            unsigned hv = __float_as_uint(ht[k * BB + b]);
            unsigned long long hd;
            asm("mov.b64 %0, {%1, %1};" : "=l"(hd) : "r"(hv));
            const ulonglong2* wrow = (const ulonglong2*)(wt + k * WSTR + cg * 8);
            ulonglong2 w0 = wrow[0];   // col pairs (0,1),(2,3)
            ulonglong2 w1 = wrow[1];   // col pairs (4,5),(6,7)
            ffma2(acc2[0], w0.x, hd);
            ffma2(acc2[1], w0.y, hd);
            ffma2(acc2[2], w1.x, hd);
            ffma2(acc2[3], w1.y, hd);
        }
    }
}

// ---------------- persistent BiLSTM kernel ----------------
__global__ void __launch_bounds__(256, 1) lstm_kernel(
    const float* __restrict__ W1f, const float* __restrict__ U1f, const float* __restrict__ b1f,
    const float* __restrict__ W2f, const float* __restrict__ U2f, const float* __restrict__ b2f,
    const float* __restrict__ W1b, const float* __restrict__ U1b, const float* __restrict__ b1b,
    const float* __restrict__ W2b, const float* __restrict__ U2b, const float* __restrict__ b2b)
{
    const int dir = blockIdx.x >> 6;     // 0 = fwd, 1 = bwd
    const int cid = blockIdx.x & 63;     // CTA within direction
    const int ub  = cid * 8;             // base hidden unit
    const int tid = threadIdx.x;
    const int b   = tid & 63;
    const int cg  = tid >> 6;            // gate: 0=i 1=f 2=g 3=o

    const float *W1, *U1, *b1, *W2, *U2, *b2;
    if (dir == 0) { W1 = W1f; U1 = U1f; b1 = b1f; W2 = W2f; U2 = U2f; b2 = b2f; }
    else          { W1 = W1b; U1 = U1b; b1 = b1b; W2 = W2b; U2 = U2b; b2 = b2b; }

    __shared__ float wt[KC * WSTR];      // 9216 B
    __shared__ float ht[KC * BB];        // 16384 B
    __shared__ float zb[GG];             // 8192 B (32 cols x 64 b as [gate*8+u][b])

    // cell state lives in registers: this thread owns pairs p=tid and p=tid+256,
    // where p = u*64 + b' (u in 0..7 local unit, b' batch)
    float c1_0 = 0.0f, c1_1 = 0.0f, c2_0 = 0.0f, c2_1 = 0.0f;
    unsigned target = 0;
    float* h1w[2] = { g_h1[dir][0], g_h1[dir][1] };
    float* h2w[2] = { g_h2[dir][0], g_h2[dir][1] };

    for (int t = 0; t < TT; t++) {
        const int ttx = dir ? (TT - 1 - t) : t;
        const int wp = t & 1, rp = wp ^ 1;

        // ================= Phase A: layer-1 gates =================
        unsigned long long acc2[4];
        #pragma unroll
        for (int j = 0; j < 4; j++) acc2[j] = 0ull;
        gemm_chunks(acc2, g_X + (size_t)ttx * EE * BB, EE, W1, ub, tid, b, cg, wt, ht);
        gemm_chunks(acc2, h1w[rp], HH, U1, ub, tid, b, cg, wt, ht);

        __syncthreads();
        #pragma unroll
        for (int j = 0; j < 4; j++) {
            float lo = __int_as_float((int)(acc2[j] & 0xffffffffull));
            float hi = __int_as_float((int)(acc2[j] >> 32));
            zb[(cg * 8 + 2 * j    ) * BB + b] = lo + b1[cg * HH + ub + 2 * j];
            zb[(cg * 8 + 2 * j + 1) * BB + b] = hi + b1[cg * HH + ub + 2 * j + 1];
        }
        __syncthreads();
        {
            // pair 0
            int u = tid >> 6, bb2 = tid & 63;
            float iv = zb[( 0 + u) * BB + bb2];
            float fv = zb[( 8 + u) * BB + bb2];
            float gv = zb[(16 + u) * BB + bb2];
            float ov = zb[(24 + u) * BB + bb2];
            float c = fsig(fv) * c1_0 + fsig(iv) * ftanh(gv);
            c1_0 = c;
            __stcg(&h1w[wp][(ub + u) * BB + bb2], fsig(ov) * ftanh(c));
            // pair 1
            u += 4;
            iv = zb[( 0 + u) * BB + bb2];
            fv = zb[( 8 + u) * BB + bb2];
            gv = zb[(16 + u) * BB + bb2];
            ov = zb[(24 + u) * BB + bb2];
            c = fsig(fv) * c1_1 + fsig(iv) * ftanh(gv);
            c1_1 = c;
            __stcg(&h1w[wp][(ub + u) * BB + bb2], fsig(ov) * ftanh(c));
        }
        target += 64;
        grid_bar(&g_bar[dir], target);

        // ================= Phase B: layer-2 gates =================
        #pragma unroll
        for (int j = 0; j < 4; j++) acc2[j] = 0ull;
        gemm_chunks(acc2, h1w[wp], HH, W2, ub, tid, b, cg, wt, ht);
        gemm_chunks(acc2, h2w[rp], HH, U2, ub, tid, b, cg, wt, ht);

        __syncthreads();
        #pragma unroll
        for (int j = 0; j < 4; j++) {
            float lo = __int_as_float((int)(acc2[j] & 0xffffffffull));
            float hi = __int_as_float((int)(acc2[j] >> 32));
            zb[(cg * 8 + 2 * j    ) * BB + b] = lo + b2[cg * HH + ub + 2 * j];
            zb[(cg * 8 + 2 * j + 1) * BB + b] = hi + b2[cg * HH + ub + 2 * j + 1];
        }
        __syncthreads();
        {
            int u = tid >> 6, bb2 = tid & 63;
            float iv = zb[( 0 + u) * BB + bb2];
            float fv = zb[( 8 + u) * BB + bb2];
            float gv = zb[(16 + u) * BB + bb2];
            float ov = zb[(24 + u) * BB + bb2];
            float c = fsig(fv) * c2_0 + fsig(iv) * ftanh(gv);
            c2_0 = c;
            __stcg(&h2w[wp][(ub + u) * BB + bb2], fsig(ov) * ftanh(c));
            u += 4;
            iv = zb[( 0 + u) * BB + bb2];
            fv = zb[( 8 + u) * BB + bb2];
            gv = zb[(16 + u) * BB + bb2];
            ov = zb[(24 + u) * BB + bb2];
            c = fsig(fv) * c2_1 + fsig(iv) * ftanh(gv);
            c2_1 = c;
            __stcg(&h2w[wp][(ub + u) * BB + bb2], fsig(ov) * ftanh(c));
        }
        target += 64;
        grid_bar(&g_bar[dir], target);
    }
}

// ---------------- final dense head ----------------
__global__ void dense_kernel(const float* __restrict__ Wd, const float* __restrict__ bd,
                             float* __restrict__ out) {
    int tid = threadIdx.x;
    if (tid >= 320) return;
    int bb2 = tid / 5, o = tid % 5;
    // last step t=511 wrote parity 1
    float s = bd[o];
    for (int j = 0; j < HH; j++) s += g_h2[0][1][j * BB + bb2] * Wd[j * 5 + o];
    for (int j = 0; j < HH; j++) s += g_h2[1][1][j * BB + bb2] * Wd[(HH + j) * 5 + o];
    out[bb2 * 5 + o] = s;
}

// ---------------- launch ----------------
extern "C" void kernel_launch(void* const* d_in, const int* in_sizes, int n_in,
                              void* d_out, int out_size) {
    const void*  tokens = d_in[0];
    const float* emb = (const float*)d_in[1];
    const float* W1f = (const float*)d_in[2];
    const float* U1f = (const float*)d_in[3];
    const float* b1f = (const float*)d_in[4];
    const float* W2f = (const float*)d_in[5];
    const float* U2f = (const float*)d_in[6];
    const float* b2f = (const float*)d_in[7];
    const float* W1b = (const float*)d_in[8];
    const float* U1b = (const float*)d_in[9];
    const float* b1b = (const float*)d_in[10];
    const float* W2b = (const float*)d_in[11];
    const float* U2b = (const float*)d_in[12];
    const float* b2b = (const float*)d_in[13];
    const float* Wd  = (const float*)d_in[14];
    const float* bd  = (const float*)d_in[15];
    float* out = (float*)d_out;

    reset_kernel<<<128, 256>>>();
    detect_kernel<<<1, 256>>>((const unsigned*)tokens);
    dim3 gg(TT, BB);
    gather_kernel<<<gg, 256>>>(tokens, emb);
    lstm_kernel<<<128, 256>>>(W1f, U1f, b1f, W2f, U2f, b2f,
                              W1b, U1b, b1b, W2b, U2b, b2b);
    dense_kernel<<<1, 320>>>(Wd, bd, out);
}

// round 12
// speedup vs baseline: 2.1403x; 2.1403x over previous
#include <cuda_runtime.h>
#include <cuda_bf16.h>
#include <math.h>

#define BB 64
#define TT 512
#define HH 512
#define WS 72            // smem row stride in bf16 (144B -> conflict-free ldmatrix)
#define KTOT 1792        // W1(256)+U1(512)+W2(512)+U2(512)

// ---------------- device scratch (allocation-free) ----------------
__device__ __nv_bfloat16 g_Wp[2][64][2][32 * KTOT];  // [dir][cta][hl][m][k]  29.4MB
__device__ __nv_bfloat16 g_Xp[TT][2][256 * 64];      // [t][hl][e][b]         33.5MB
__device__ __nv_bfloat16 g_hs[2][2][2][2][HH * 64];  // [dir][layer][par][hl][k][b]
__device__ float g_h2f[2][HH * 64];
__device__ unsigned g_bar[2];
__device__ int g_tok32;

// ---------------- helpers ----------------
__device__ __forceinline__ float fsig(float x) { return 1.0f / (1.0f + __expf(-x)); }
__device__ __forceinline__ float ftanh(float x) { return 2.0f / (1.0f + __expf(-2.0f * x)) - 1.0f; }
__device__ __forceinline__ unsigned smem_u32(const void* p) {
    unsigned a;
    asm("{ .reg .u64 t; cvta.to.shared.u64 t, %1; cvt.u32.u64 %0, t; }" : "=r"(a) : "l"(p));
    return a;
}
__device__ __forceinline__ void ldsm4(unsigned* r, unsigned a) {
    asm volatile("ldmatrix.sync.aligned.m8n8.x4.shared.b16 {%0,%1,%2,%3}, [%4];"
                 : "=r"(r[0]), "=r"(r[1]), "=r"(r[2]), "=r"(r[3]) : "r"(a));
}
__device__ __forceinline__ void ldsm4t(unsigned* r, unsigned a) {
    asm volatile("ldmatrix.sync.aligned.m8n8.x4.trans.shared.b16 {%0,%1,%2,%3}, [%4];"
                 : "=r"(r[0]), "=r"(r[1]), "=r"(r[2]), "=r"(r[3]) : "r"(a));
}
__device__ __forceinline__ void mma4(float* d, const unsigned* a, const unsigned* b) {
    asm volatile("mma.sync.aligned.m16n8k16.row.col.f32.bf16.bf16.f32 "
                 "{%0,%1,%2,%3}, {%4,%5,%6,%7}, {%8,%9}, {%0,%1,%2,%3};"
                 : "+f"(d[0]), "+f"(d[1]), "+f"(d[2]), "+f"(d[3])
                 : "r"(a[0]), "r"(a[1]), "r"(a[2]), "r"(a[3]), "r"(b[0]), "r"(b[1]));
}
__device__ __forceinline__ void grid_bar(unsigned* ctr, unsigned target) {
    __syncthreads();
    if (threadIdx.x == 0) {
        __threadfence();
        atomicAdd(ctr, 1u);
        while (*((volatile unsigned*)ctr) < target) { }
    }
    __syncthreads();
}

// ---------------- reset ----------------
__global__ void reset_kernel() {
    unsigned i = blockIdx.x * blockDim.x + threadIdx.x;
    unsigned* p = (unsigned*)g_hs;
    for (unsigned j = i; j < sizeof(g_hs) / 4; j += 32768) p[j] = 0;
    if (i == 0) { g_bar[0] = 0u; g_bar[1] = 0u; }
}

// ---------------- token dtype detect ----------------
__global__ void detect_kernel(const unsigned* tok) {
    __shared__ unsigned red[256];
    unsigned v = 0;
    for (int i = threadIdx.x; i < 16384; i += 256) v |= tok[2 * i + 1];
    red[threadIdx.x] = v;
    __syncthreads();
    for (int s = 128; s > 0; s >>= 1) {
        if (threadIdx.x < s) red[threadIdx.x] |= red[threadIdx.x + s];
        __syncthreads();
    }
    if (threadIdx.x == 0) g_tok32 = (red[0] != 0u) ? 1 : 0;
}

// ---------------- embedding gather -> [t][hl][e][b] bf16 ----------------
__global__ void gather_kernel(const void* tokens, const float* emb) {
    int t = blockIdx.x, eg = blockIdx.y;           // eg 0..31
    int wid = threadIdx.x >> 5, lane = threadIdx.x & 31;
    int e = eg * 8 + wid;
    #pragma unroll
    for (int j = 0; j < 2; j++) {
        int b = lane + j * 32;
        long idx;
        if (g_tok32) idx = (long)((const int*)tokens)[b * TT + t];
        else         idx = (long)((const unsigned*)tokens)[(size_t)(b * TT + t) * 2];
        float v = emb[idx * 256 + e];
        __nv_bfloat16 hi = __float2bfloat16(v);
        g_Xp[t][0][e * 64 + b] = hi;
        g_Xp[t][1][e * 64 + b] = __float2bfloat16(v - __bfloat162float(hi));
    }
}

// ---------------- weight prepack: [dir][cta][hl][m 0-31][k 0-1791] ----------------
__global__ void wpack_kernel(const float* W1f, const float* U1f, const float* W2f, const float* U2f,
                             const float* W1b, const float* U1b, const float* W2b, const float* U2b) {
    int cid = blockIdx.x & 63, dir = blockIdx.x >> 6;
    const float *W1 = dir ? W1b : W1f, *U1 = dir ? U1b : U1f;
    const float *W2 = dir ? W2b : W2f, *U2 = dir ? U2b : U2f;
    __nv_bfloat16* d0 = g_Wp[dir][cid][0];
    __nv_bfloat16* d1 = g_Wp[dir][cid][1];
    for (int idx = threadIdx.x; idx < 32 * KTOT; idx += 256) {
        int m = idx / KTOT, k = idx % KTOT;
        const float* M; int kk;
        if (k < 256)       { M = W1; kk = k; }
        else if (k < 768)  { M = U1; kk = k - 256; }
        else if (k < 1280) { M = W2; kk = k - 768; }
        else               { M = U2; kk = k - 1280; }
        int col = (m >> 3) * 512 + cid * 8 + (m & 7);   // gate*512 + unit
        float w = M[(size_t)kk * 2048 + col];
        __nv_bfloat16 hi = __float2bfloat16(w);
        d0[idx] = hi;
        d1[idx] = __float2bfloat16(w - __bfloat162float(hi));
    }
}

// ---------------- persistent HMMA BiLSTM ----------------
__global__ void __launch_bounds__(256, 1) lstm_kernel(
    const float* __restrict__ b1f, const float* __restrict__ b2f,
    const float* __restrict__ b1b, const float* __restrict__ b2b)
{
    const int dir = blockIdx.x >> 6, cid = blockIdx.x & 63;
    const int ub = cid * 8;
    const int tid = threadIdx.x, lane = tid & 31, wid = tid >> 5;
    const int mbase = (wid & 1) * 16, nbase = (wid >> 1) * 16;

    __shared__ __nv_bfloat16 sW[2][32 * WS];
    __shared__ __nv_bfloat16 sH[2][64 * WS];
    __shared__ float zb[32 * 65];

    const unsigned aW0 = smem_u32(sW[0]), aW1 = smem_u32(sW[1]);
    const unsigned aH0 = smem_u32(sH[0]), aH1 = smem_u32(sH[1]);
    // ldmatrix lane byte-offsets
    const unsigned a_off = ((mbase + ((lane >> 3) & 1) * 8 + (lane & 7)) * WS + (lane >> 4) * 8) * 2;
    const unsigned b_off = ((((lane >> 3) & 1) * 8 + (lane & 7)) * WS + nbase + (lane >> 4) * 8) * 2;

    const float* b1 = dir ? b1b : b1f;
    const float* b2 = dir ? b2b : b2f;
    const int pu = wid;                 // pointwise unit 0..7 (one per warp)
    const int pb = lane * 2;            // 2 batches per thread
    float bias1[4], bias2[4];
    #pragma unroll
    for (int g = 0; g < 4; g++) {
        bias1[g] = b1[g * 512 + ub + pu];
        bias2[g] = b2[g * 512 + ub + pu];
    }

    const __nv_bfloat16* Wp0 = g_Wp[dir][cid][0];
    const __nv_bfloat16* Wp1 = g_Wp[dir][cid][1];
    const int wrow = tid >> 3, wseg = tid & 7;

    float c1[2] = {0.f, 0.f}, c2[2] = {0.f, 0.f};
    unsigned target = 0;

    for (int t = 0; t < TT; t++) {
        const int ttx = dir ? (TT - 1 - t) : t;
        const int wp = t & 1, rp = wp ^ 1;
        for (int ph = 0; ph < 2; ph++) {
            float dn0[4] = {0.f, 0.f, 0.f, 0.f};
            float dn1[4] = {0.f, 0.f, 0.f, 0.f};
            const int nch = ph ? 16 : 12;
            for (int c = 0; c < nch; c++) {
                int kofs;
                const __nv_bfloat16 *bs0, *bs1;
                if (ph == 0) {
                    if (c < 4) { kofs = c * 64;           bs0 = g_Xp[ttx][0] + c * 4096;          bs1 = g_Xp[ttx][1] + c * 4096; }
                    else       { kofs = 256 + (c - 4) * 64; bs0 = g_hs[dir][0][rp][0] + (c - 4) * 4096; bs1 = g_hs[dir][0][rp][1] + (c - 4) * 4096; }
                } else {
                    if (c < 8) { kofs = 768 + c * 64;     bs0 = g_hs[dir][0][wp][0] + c * 4096;   bs1 = g_hs[dir][0][wp][1] + c * 4096; }
                    else       { kofs = 1280 + (c - 8) * 64; bs0 = g_hs[dir][1][rp][0] + (c - 8) * 4096; bs1 = g_hs[dir][1][rp][1] + (c - 8) * 4096; }
                }
                // register prefetch (coalesced)
                float4 w0 = *(const float4*)(Wp0 + (size_t)wrow * KTOT + kofs + wseg * 8);
                float4 w1 = *(const float4*)(Wp1 + (size_t)wrow * KTOT + kofs + wseg * 8);
                float4 ha0 = __ldcg((const float4*)(bs0 + tid * 8));
                float4 ha1 = __ldcg((const float4*)(bs0 + 2048 + tid * 8));
                float4 hb0 = __ldcg((const float4*)(bs1 + tid * 8));
                float4 hb1 = __ldcg((const float4*)(bs1 + 2048 + tid * 8));
                __syncthreads();
                *(float4*)&sW[0][wrow * WS + wseg * 8] = w0;
                *(float4*)&sW[1][wrow * WS + wseg * 8] = w1;
                *(float4*)&sH[0][(tid >> 3) * WS + (tid & 7) * 8] = ha0;
                *(float4*)&sH[0][((tid >> 3) + 32) * WS + (tid & 7) * 8] = ha1;
                *(float4*)&sH[1][(tid >> 3) * WS + (tid & 7) * 8] = hb0;
                *(float4*)&sH[1][((tid >> 3) + 32) * WS + (tid & 7) * 8] = hb1;
                __syncthreads();
                #pragma unroll
                for (int k16 = 0; k16 < 4; k16++) {
                    unsigned ah[4], al[4], bh[4], bl[4];
                    ldsm4(ah, aW0 + a_off + k16 * 32);
                    ldsm4(al, aW1 + a_off + k16 * 32);
                    ldsm4t(bh, aH0 + b_off + k16 * 16 * WS * 2);
                    ldsm4t(bl, aH1 + b_off + k16 * 16 * WS * 2);
                    mma4(dn0, ah, bh); mma4(dn1, ah, bh + 2);
                    mma4(dn0, al, bh); mma4(dn1, al, bh + 2);
                    mma4(dn0, ah, bl); mma4(dn1, ah, bl + 2);
                }
            }
            // ---------- epilogue: accums -> zb ----------
            {
                int r = lane >> 2, cp = (lane & 3) * 2;
                zb[(mbase + r) * 65 + nbase + cp]         = dn0[0];
                zb[(mbase + r) * 65 + nbase + cp + 1]     = dn0[1];
                zb[(mbase + 8 + r) * 65 + nbase + cp]     = dn0[2];
                zb[(mbase + 8 + r) * 65 + nbase + cp + 1] = dn0[3];
                zb[(mbase + r) * 65 + nbase + 8 + cp]         = dn1[0];
                zb[(mbase + r) * 65 + nbase + 8 + cp + 1]     = dn1[1];
                zb[(mbase + 8 + r) * 65 + nbase + 8 + cp]     = dn1[2];
                zb[(mbase + 8 + r) * 65 + nbase + 8 + cp + 1] = dn1[3];
            }
            __syncthreads();
            // ---------- pointwise ----------
            {
                float* cc = ph ? c2 : c1;
                const float* bias = ph ? bias2 : bias1;
                __nv_bfloat16* h0 = g_hs[dir][ph][wp][0];
                __nv_bfloat16* h1 = g_hs[dir][ph][wp][1];
                #pragma unroll
                for (int j = 0; j < 2; j++) {
                    int b = pb + j;
                    float iv = zb[pu * 65 + b]        + bias[0];
                    float fv = zb[(8 + pu) * 65 + b]  + bias[1];
                    float gv = zb[(16 + pu) * 65 + b] + bias[2];
                    float ov = zb[(24 + pu) * 65 + b] + bias[3];
                    cc[j] = fsig(fv) * cc[j] + fsig(iv) * ftanh(gv);
                    float h = fsig(ov) * ftanh(cc[j]);
                    __nv_bfloat16 hi = __float2bfloat16(h);
                    h0[(ub + pu) * 64 + b] = hi;
                    h1[(ub + pu) * 64 + b] = __float2bfloat16(h - __bfloat162float(hi));
                    if (ph && t == TT - 1) g_h2f[dir][(ub + pu) * 64 + b] = h;
                }
            }
            target += 64;
            grid_bar(&g_bar[dir], target);
        }
    }
}

// ---------------- final dense head ----------------
__global__ void dense_kernel(const float* __restrict__ Wd, const float* __restrict__ bd,
                             float* __restrict__ out) {
    int tid = threadIdx.x;
    if (tid >= 320) return;
    int b = tid / 5, o = tid % 5;
    float s = bd[o];
    for (int j = 0; j < HH; j++) s += g_h2f[0][j * 64 + b] * Wd[j * 5 + o];
    for (int j = 0; j < HH; j++) s += g_h2f[1][j * 64 + b] * Wd[(HH + j) * 5 + o];
    out[b * 5 + o] = s;
}

// ---------------- launch ----------------
extern "C" void kernel_launch(void* const* d_in, const int* in_sizes, int n_in,
                              void* d_out, int out_size) {
    const void*  tokens = d_in[0];
    const float* emb = (const float*)d_in[1];
    const float* W1f = (const float*)d_in[2];
    const float* U1f = (const float*)d_in[3];
    const float* b1f = (const float*)d_in[4];
    const float* W2f = (const float*)d_in[5];
    const float* U2f = (const float*)d_in[6];
    const float* b2f = (const float*)d_in[7];
    const float* W1b = (const float*)d_in[8];
    const float* U1b = (const float*)d_in[9];
    const float* b1b = (const float*)d_in[10];
    const float* W2b = (const float*)d_in[11];
    const float* U2b = (const float*)d_in[12];
    const float* b2b = (const float*)d_in[13];
    const float* Wd  = (const float*)d_in[14];
    const float* bd  = (const float*)d_in[15];
    float* out = (float*)d_out;

    reset_kernel<<<128, 256>>>();
    detect_kernel<<<1, 256>>>((const unsigned*)tokens);
    dim3 gg(TT, 32);
    gather_kernel<<<gg, 256>>>(tokens, emb);
    wpack_kernel<<<128, 256>>>(W1f, U1f, W2f, U2f, W1b, U1b, W2b, U2b);
    lstm_kernel<<<128, 256>>>(b1f, b2f, b1b, b2b);
    dense_kernel<<<1, 320>>>(Wd, bd, out);
}

// round 13
// speedup vs baseline: 2.7740x; 1.2961x over previous
#include <cuda_runtime.h>
#include <cuda_bf16.h>
#include <math.h>

#define BB 64
#define TT 512
#define HH 512
#define WS 72            // smem row stride in bf16 (144B -> conflict-free ldmatrix)
#define KTOT 1792        // W1(256)+U1(512)+W2(512)+U2(512)
#define WTILE (32 * WS)  // 2304 bf16 per (buf,hl) weight tile
#define HTILE (64 * WS)  // 4608 bf16 per (buf,hl) h tile
#define SMEM_DYN ((4 * WTILE + 4 * HTILE) * 2 + 32 * 65 * 4)   // 63616 B

// ---------------- device scratch (allocation-free) ----------------
__device__ __nv_bfloat16 g_Wp[2][64][2][32 * KTOT];  // [dir][cta][hl][m][k]
__device__ __nv_bfloat16 g_Xp[TT][2][256 * 64];      // [t][hl][e][b]
__device__ __nv_bfloat16 g_hs[2][2][2][2][HH * 64];  // [dir][layer][par][hl][k][b]
__device__ float g_h2f[2][HH * 64];
__device__ unsigned g_bar[2];
__device__ int g_tok32;

// ---------------- helpers ----------------
__device__ __forceinline__ float fsig(float x) { return 1.0f / (1.0f + __expf(-x)); }
__device__ __forceinline__ float ftanh(float x) { return 2.0f / (1.0f + __expf(-2.0f * x)) - 1.0f; }
__device__ __forceinline__ unsigned smem_u32(const void* p) {
    unsigned a;
    asm("{ .reg .u64 t; cvta.to.shared.u64 t, %1; cvt.u32.u64 %0, t; }" : "=r"(a) : "l"(p));
    return a;
}
__device__ __forceinline__ void ldsm4(unsigned* r, unsigned a) {
    asm volatile("ldmatrix.sync.aligned.m8n8.x4.shared.b16 {%0,%1,%2,%3}, [%4];"
                 : "=r"(r[0]), "=r"(r[1]), "=r"(r[2]), "=r"(r[3]) : "r"(a));
}
__device__ __forceinline__ void ldsm4t(unsigned* r, unsigned a) {
    asm volatile("ldmatrix.sync.aligned.m8n8.x4.trans.shared.b16 {%0,%1,%2,%3}, [%4];"
                 : "=r"(r[0]), "=r"(r[1]), "=r"(r[2]), "=r"(r[3]) : "r"(a));
}
__device__ __forceinline__ void mma4(float* d, const unsigned* a, const unsigned* b) {
    asm volatile("mma.sync.aligned.m16n8k16.row.col.f32.bf16.bf16.f32 "
                 "{%0,%1,%2,%3}, {%4,%5,%6,%7}, {%8,%9}, {%0,%1,%2,%3};"
                 : "+f"(d[0]), "+f"(d[1]), "+f"(d[2]), "+f"(d[3])
                 : "r"(a[0]), "r"(a[1]), "r"(a[2]), "r"(a[3]), "r"(b[0]), "r"(b[1]));
}
__device__ __forceinline__ void grid_bar(unsigned* ctr, unsigned target) {
    __syncthreads();
    if (threadIdx.x == 0) {
        __threadfence();
        atomicAdd(ctr, 1u);
        while (*((volatile unsigned*)ctr) < target) { }
    }
    __syncthreads();
}

// ---------------- reset ----------------
__global__ void reset_kernel() {
    unsigned i = blockIdx.x * blockDim.x + threadIdx.x;
    unsigned* p = (unsigned*)g_hs;
    for (unsigned j = i; j < sizeof(g_hs) / 4; j += 32768) p[j] = 0;
    if (i == 0) { g_bar[0] = 0u; g_bar[1] = 0u; }
}

// ---------------- token dtype detect ----------------
__global__ void detect_kernel(const unsigned* tok) {
    __shared__ unsigned red[256];
    unsigned v = 0;
    for (int i = threadIdx.x; i < 16384; i += 256) v |= tok[2 * i + 1];
    red[threadIdx.x] = v;
    __syncthreads();
    for (int s = 128; s > 0; s >>= 1) {
        if (threadIdx.x < s) red[threadIdx.x] |= red[threadIdx.x + s];
        __syncthreads();
    }
    if (threadIdx.x == 0) g_tok32 = (red[0] != 0u) ? 1 : 0;
}

// ---------------- embedding gather -> [t][hl][e][b] bf16 ----------------
__global__ void gather_kernel(const void* tokens, const float* emb) {
    int t = blockIdx.x, eg = blockIdx.y;
    int wid = threadIdx.x >> 5, lane = threadIdx.x & 31;
    int e = eg * 8 + wid;
    #pragma unroll
    for (int j = 0; j < 2; j++) {
        int b = lane + j * 32;
        long idx;
        if (g_tok32) idx = (long)((const int*)tokens)[b * TT + t];
        else         idx = (long)((const unsigned*)tokens)[(size_t)(b * TT + t) * 2];
        float v = emb[idx * 256 + e];
        __nv_bfloat16 hi = __float2bfloat16(v);
        g_Xp[t][0][e * 64 + b] = hi;
        g_Xp[t][1][e * 64 + b] = __float2bfloat16(v - __bfloat162float(hi));
    }
}

// ---------------- weight prepack ----------------
__global__ void wpack_kernel(const float* W1f, const float* U1f, const float* W2f, const float* U2f,
                             const float* W1b, const float* U1b, const float* W2b, const float* U2b) {
    int cid = blockIdx.x & 63, dir = blockIdx.x >> 6;
    const float *W1 = dir ? W1b : W1f, *U1 = dir ? U1b : U1f;
    const float *W2 = dir ? W2b : W2f, *U2 = dir ? U2b : U2f;
    __nv_bfloat16* d0 = g_Wp[dir][cid][0];
    __nv_bfloat16* d1 = g_Wp[dir][cid][1];
    for (int idx = threadIdx.x; idx < 32 * KTOT; idx += 256) {
        int m = idx / KTOT, k = idx % KTOT;
        const float* M; int kk;
        if (k < 256)       { M = W1; kk = k; }
        else if (k < 768)  { M = U1; kk = k - 256; }
        else if (k < 1280) { M = W2; kk = k - 768; }
        else               { M = U2; kk = k - 1280; }
        int col = (m >> 3) * 512 + cid * 8 + (m & 7);
        float w = M[(size_t)kk * 2048 + col];
        __nv_bfloat16 hi = __float2bfloat16(w);
        d0[idx] = hi;
        d1[idx] = __float2bfloat16(w - __bfloat162float(hi));
    }
}

// ---------------- persistent HMMA BiLSTM (double-buffered) ----------------
__global__ void __launch_bounds__(256, 1) lstm_kernel(
    const float* __restrict__ b1f, const float* __restrict__ b2f,
    const float* __restrict__ b1b, const float* __restrict__ b2b)
{
    const int dir = blockIdx.x >> 6, cid = blockIdx.x & 63;
    const int ub = cid * 8;
    const int tid = threadIdx.x, lane = tid & 31, wid = tid >> 5;
    const int mbase = (wid & 1) * 16, nbase = (wid >> 1) * 16;

    extern __shared__ __nv_bfloat16 dsm[];
    __nv_bfloat16* sWb = dsm;                       // [buf][hl] x WTILE
    __nv_bfloat16* sHb = dsm + 4 * WTILE;           // [buf][hl] x HTILE
    float* zb = (float*)(dsm + 4 * WTILE + 4 * HTILE);

    const unsigned aWbase = smem_u32(sWb);
    const unsigned aHbase = smem_u32(sHb);
    const unsigned a_off = ((mbase + ((lane >> 3) & 1) * 8 + (lane & 7)) * WS + (lane >> 4) * 8) * 2;
    const unsigned b_off = ((((lane >> 3) & 1) * 8 + (lane & 7)) * WS + nbase + (lane >> 4) * 8) * 2;

    const float* b1 = dir ? b1b : b1f;
    const float* b2 = dir ? b2b : b2f;
    const int pu = wid;
    const int pb = lane * 2;
    float bias1[4], bias2[4];
    #pragma unroll
    for (int g = 0; g < 4; g++) {
        bias1[g] = b1[g * 512 + ub + pu];
        bias2[g] = b2[g * 512 + ub + pu];
    }

    const __nv_bfloat16* Wp0 = g_Wp[dir][cid][0];
    const __nv_bfloat16* Wp1 = g_Wp[dir][cid][1];
    const int wrow = tid >> 3, wseg = tid & 7;

    float c1[2] = {0.f, 0.f}, c2[2] = {0.f, 0.f};
    unsigned target = 0;

    for (int t = 0; t < TT; t++) {
        const int ttx = dir ? (TT - 1 - t) : t;
        const int wp = t & 1, rp = wp ^ 1;
        for (int ph = 0; ph < 2; ph++) {
            float dn0[4] = {0.f, 0.f, 0.f, 0.f};
            float dn1[4] = {0.f, 0.f, 0.f, 0.f};
            const int nch = ph ? 16 : 12;

            // source resolver for chunk c of this phase
            auto src_of = [&](int c, int& kofs, const __nv_bfloat16*& s0, const __nv_bfloat16*& s1) {
                if (ph == 0) {
                    if (c < 4) { kofs = c * 64;             s0 = g_Xp[ttx][0] + c * 4096;              s1 = g_Xp[ttx][1] + c * 4096; }
                    else       { kofs = 256 + (c - 4) * 64; s0 = g_hs[dir][0][rp][0] + (c - 4) * 4096; s1 = g_hs[dir][0][rp][1] + (c - 4) * 4096; }
                } else {
                    if (c < 8) { kofs = 768 + c * 64;        s0 = g_hs[dir][0][wp][0] + c * 4096;       s1 = g_hs[dir][0][wp][1] + c * 4096; }
                    else       { kofs = 1280 + (c - 8) * 64; s0 = g_hs[dir][1][rp][0] + (c - 8) * 4096; s1 = g_hs[dir][1][rp][1] + (c - 8) * 4096; }
                }
            };

            // ---- prologue: stage chunk 0 into buf 0 ----
            {
                int kofs; const __nv_bfloat16 *bs0, *bs1;
                src_of(0, kofs, bs0, bs1);
                float4 w0 = *(const float4*)(Wp0 + (size_t)wrow * KTOT + kofs + wseg * 8);
                float4 w1 = *(const float4*)(Wp1 + (size_t)wrow * KTOT + kofs + wseg * 8);
                float4 ha0 = __ldcg((const float4*)(bs0 + tid * 8));
                float4 ha1 = __ldcg((const float4*)(bs0 + 2048 + tid * 8));
                float4 hb0 = __ldcg((const float4*)(bs1 + tid * 8));
                float4 hb1 = __ldcg((const float4*)(bs1 + 2048 + tid * 8));
                *(float4*)&sWb[0 * WTILE + wrow * WS + wseg * 8] = w0;
                *(float4*)&sWb[1 * WTILE + wrow * WS + wseg * 8] = w1;
                *(float4*)&sHb[0 * HTILE + (tid >> 3) * WS + (tid & 7) * 8] = ha0;
                *(float4*)&sHb[0 * HTILE + ((tid >> 3) + 32) * WS + (tid & 7) * 8] = ha1;
                *(float4*)&sHb[1 * HTILE + (tid >> 3) * WS + (tid & 7) * 8] = hb0;
                *(float4*)&sHb[1 * HTILE + ((tid >> 3) + 32) * WS + (tid & 7) * 8] = hb1;
                __syncthreads();
            }

            for (int c = 0; c < nch; c++) {
                const int buf = c & 1, nbuf = buf ^ 1;
                // prefetch next chunk into registers
                float4 w0, w1, ha0, ha1, hb0, hb1;
                const bool more = (c + 1 < nch);
                if (more) {
                    int kofs; const __nv_bfloat16 *bs0, *bs1;
                    src_of(c + 1, kofs, bs0, bs1);
                    w0 = *(const float4*)(Wp0 + (size_t)wrow * KTOT + kofs + wseg * 8);
                    w1 = *(const float4*)(Wp1 + (size_t)wrow * KTOT + kofs + wseg * 8);
                    ha0 = __ldcg((const float4*)(bs0 + tid * 8));
                    ha1 = __ldcg((const float4*)(bs0 + 2048 + tid * 8));
                    hb0 = __ldcg((const float4*)(bs1 + tid * 8));
                    hb1 = __ldcg((const float4*)(bs1 + 2048 + tid * 8));
                }
                // MMA on current buffer
                const unsigned aW0 = aWbase + (buf * 2 + 0) * WTILE * 2;
                const unsigned aW1 = aWbase + (buf * 2 + 1) * WTILE * 2;
                const unsigned aH0 = aHbase + (buf * 2 + 0) * HTILE * 2;
                const unsigned aH1 = aHbase + (buf * 2 + 1) * HTILE * 2;
                #pragma unroll
                for (int k16 = 0; k16 < 4; k16++) {
                    unsigned ah[4], al[4], bh[4], bl[4];
                    ldsm4(ah, aW0 + a_off + k16 * 32);
                    ldsm4(al, aW1 + a_off + k16 * 32);
                    ldsm4t(bh, aH0 + b_off + k16 * 16 * WS * 2);
                    ldsm4t(bl, aH1 + b_off + k16 * 16 * WS * 2);
                    mma4(dn0, ah, bh); mma4(dn1, ah, bh + 2);
                    mma4(dn0, al, bh); mma4(dn1, al, bh + 2);
                    mma4(dn0, ah, bl); mma4(dn1, ah, bl + 2);
                }
                // store next chunk into the other buffer
                if (more) {
                    *(float4*)&sWb[(nbuf * 2 + 0) * WTILE + wrow * WS + wseg * 8] = w0;
                    *(float4*)&sWb[(nbuf * 2 + 1) * WTILE + wrow * WS + wseg * 8] = w1;
                    *(float4*)&sHb[(nbuf * 2 + 0) * HTILE + (tid >> 3) * WS + (tid & 7) * 8] = ha0;
                    *(float4*)&sHb[(nbuf * 2 + 0) * HTILE + ((tid >> 3) + 32) * WS + (tid & 7) * 8] = ha1;
                    *(float4*)&sHb[(nbuf * 2 + 1) * HTILE + (tid >> 3) * WS + (tid & 7) * 8] = hb0;
                    *(float4*)&sHb[(nbuf * 2 + 1) * HTILE + ((tid >> 3) + 32) * WS + (tid & 7) * 8] = hb1;
                }
                __syncthreads();
            }
            // ---------- epilogue: accums -> zb ----------
            {
                int r = lane >> 2, cp = (lane & 3) * 2;
                zb[(mbase + r) * 65 + nbase + cp]         = dn0[0];
                zb[(mbase + r) * 65 + nbase + cp + 1]     = dn0[1];
                zb[(mbase + 8 + r) * 65 + nbase + cp]     = dn0[2];
                zb[(mbase + 8 + r) * 65 + nbase + cp + 1] = dn0[3];
                zb[(mbase + r) * 65 + nbase + 8 + cp]         = dn1[0];
                zb[(mbase + r) * 65 + nbase + 8 + cp + 1]     = dn1[1];
                zb[(mbase + 8 + r) * 65 + nbase + 8 + cp]     = dn1[2];
                zb[(mbase + 8 + r) * 65 + nbase + 8 + cp + 1] = dn1[3];
            }
            __syncthreads();
            // ---------- pointwise ----------
            {
                float* cc = ph ? c2 : c1;
                const float* bias = ph ? bias2 : bias1;
                __nv_bfloat16* h0 = g_hs[dir][ph][wp][0];
                __nv_bfloat16* h1 = g_hs[dir][ph][wp][1];
                #pragma unroll
                for (int j = 0; j < 2; j++) {
                    int b = pb + j;
                    float iv = zb[pu * 65 + b]        + bias[0];
                    float fv = zb[(8 + pu) * 65 + b]  + bias[1];
                    float gv = zb[(16 + pu) * 65 + b] + bias[2];
                    float ov = zb[(24 + pu) * 65 + b] + bias[3];
                    cc[j] = fsig(fv) * cc[j] + fsig(iv) * ftanh(gv);
                    float h = fsig(ov) * ftanh(cc[j]);
                    __nv_bfloat16 hi = __float2bfloat16(h);
                    h0[(ub + pu) * 64 + b] = hi;
                    h1[(ub + pu) * 64 + b] = __float2bfloat16(h - __bfloat162float(hi));
                    if (ph && t == TT - 1) g_h2f[dir][(ub + pu) * 64 + b] = h;
                }
            }
            target += 64;
            grid_bar(&g_bar[dir], target);
        }
    }
}

// ---------------- final dense head ----------------
__global__ void dense_kernel(const float* __restrict__ Wd, const float* __restrict__ bd,
                             float* __restrict__ out) {
    int tid = threadIdx.x;
    if (tid >= 320) return;
    int b = tid / 5, o = tid % 5;
    float s = bd[o];
    for (int j = 0; j < HH; j++) s += g_h2f[0][j * 64 + b] * Wd[j * 5 + o];
    for (int j = 0; j < HH; j++) s += g_h2f[1][j * 64 + b] * Wd[(HH + j) * 5 + o];
    out[b * 5 + o] = s;
}

// ---------------- launch ----------------
extern "C" void kernel_launch(void* const* d_in, const int* in_sizes, int n_in,
                              void* d_out, int out_size) {
    const void*  tokens = d_in[0];
    const float* emb = (const float*)d_in[1];
    const float* W1f = (const float*)d_in[2];
    const float* U1f = (const float*)d_in[3];
    const float* b1f = (const float*)d_in[4];
    const float* W2f = (const float*)d_in[5];
    const float* U2f = (const float*)d_in[6];
    const float* b2f = (const float*)d_in[7];
    const float* W1b = (const float*)d_in[8];
    const float* U1b = (const float*)d_in[9];
    const float* b1b = (const float*)d_in[10];
    const float* W2b = (const float*)d_in[11];
    const float* U2b = (const float*)d_in[12];
    const float* b2b = (const float*)d_in[13];
    const float* Wd  = (const float*)d_in[14];
    const float* bd  = (const float*)d_in[15];
    float* out = (float*)d_out;

    cudaFuncSetAttribute(lstm_kernel, cudaFuncAttributeMaxDynamicSharedMemorySize, SMEM_DYN);
    reset_kernel<<<128, 256>>>();
    detect_kernel<<<1, 256>>>((const unsigned*)tokens);
    dim3 gg(TT, 32);
    gather_kernel<<<gg, 256>>>(tokens, emb);
    wpack_kernel<<<128, 256>>>(W1f, U1f, W2f, U2f, W1b, U1b, W2b, U2b);
    lstm_kernel<<<128, 256, SMEM_DYN>>>(b1f, b2f, b1b, b2b);
    dense_kernel<<<1, 320>>>(Wd, bd, out);
}